// round 9
// baseline (speedup 1.0000x reference)
#include <cuda_runtime.h>
#include <math.h>

#define CC 256
#define HH 4
#define NMAX 500000
#define PMAX 50000
#define TP 16

typedef unsigned long long ull;

// ---------------- device scratch ----------------
__device__ float    g_Q[CC];
__device__ float    g_qw[HH * CC];
__device__ float    g_qc[HH];
__device__ float    g_scoreE[(size_t)NMAX * HH];          // raw scores
__device__ unsigned g_smax[PMAX * HH];
__device__ float    g_m[(PMAX + 32) * HH];                // m = d/(d+eps); padded
__device__ int      g_head[PMAX];                         // linked-list heads
__device__ int      g_next[NMAX];
__device__ float    g_xbar[(size_t)(PMAX + 32) * HH * CC]; // pre-normalized; padded

// ---------------- helpers ----------------
__device__ __forceinline__ unsigned encf(float f) {
    unsigned u = __float_as_uint(f);
    return (u & 0x80000000u) ? ~u : (u | 0x80000000u);
}
__device__ __forceinline__ float decf(unsigned u) {
    return (u & 0x80000000u) ? __uint_as_float(u ^ 0x80000000u) : __uint_as_float(~u);
}
__device__ __forceinline__ float hadd2(ull v) {
    float x, y;
    asm("mov.b64 {%0,%1}, %2;" : "=f"(x), "=f"(y) : "l"(v));
    return x + y;
}
__device__ __forceinline__ void fma2(ull& d, ull a, ull b) {
    asm("fma.rn.f32x2 %0, %1, %2, %0;" : "+l"(d) : "l"(a), "l"(b));
}

// ---------------- kernels ----------------

// block 0: Q = S@Wq^T+bq, qw/qc.  blocks 1..: clear smax/head.
__global__ void k_init_prep(const float* __restrict__ S, const float* __restrict__ Wq,
                            const float* __restrict__ bq, const float* __restrict__ Wk,
                            const float* __restrict__ bk, int P)
{
    int t = threadIdx.x;
    if (blockIdx.x == 0) {
        __shared__ float sS[CC];
        __shared__ float sQ[CC];
        sS[t] = S[t];
        __syncthreads();
        const float4* wr = (const float4*)(Wq + (size_t)t * CC);
        float acc = 0.f;
        #pragma unroll 8
        for (int j = 0; j < CC / 4; j++) {
            float4 w = wr[j];
            acc += sS[4*j] * w.x + sS[4*j+1] * w.y + sS[4*j+2] * w.z + sS[4*j+3] * w.w;
        }
        acc += bq[t];
        sQ[t] = acc;
        g_Q[t] = acc;
        __syncthreads();
        #pragma unroll
        for (int h = 0; h < HH; h++) {
            float a = 0.f;
            #pragma unroll 8
            for (int cc = 0; cc < 64; cc++)
                a += sQ[h * 64 + cc] * Wk[(size_t)(h * 64 + cc) * CC + t];
            g_qw[h * CC + t] = a * 0.0625f;
        }
        if (t < HH) {
            float q = 0.f;
            for (int cc = 0; cc < 64; cc++) q += sQ[t * 64 + cc] * bk[t * 64 + cc];
            g_qc[t] = q * 0.0625f;
        }
    } else {
        int i = (blockIdx.x - 1) * blockDim.x + t;
        int st = (gridDim.x - 1) * blockDim.x;
        for (int j = i; j < P * HH; j += st) g_smax[j] = 0u;
        for (int j = i; j < P; j += st) g_head[j] = -1;
    }
}

// warp handles 4 checkins (MLP=8); also pushes n onto POI linked list.
__global__ void __launch_bounds__(256) k_scores(
    const float* __restrict__ x, const int* __restrict__ poi, int N)
{
    __shared__ float sq[HH * CC];
    __shared__ float sqc[HH];
    int t = threadIdx.x;
    *(float4*)&sq[t * 4] = *(const float4*)&g_qw[t * 4];
    if (t < HH) sqc[t] = g_qc[t];
    __syncthreads();

    int lane = t & 31;
    int gw = (blockIdx.x * blockDim.x + t) >> 5;
    int n0 = gw * 4;
    if (n0 >= N) return;
    int nA = n0, nB = min(n0 + 1, N - 1), nC = min(n0 + 2, N - 1), nD = min(n0 + 3, N - 1);

    const float4* xA = (const float4*)(x + (size_t)nA * CC);
    const float4* xB = (const float4*)(x + (size_t)nB * CC);
    const float4* xC = (const float4*)(x + (size_t)nC * CC);
    const float4* xD = (const float4*)(x + (size_t)nD * CC);
    float4 A0 = xA[lane], A1 = xA[32 + lane];
    float4 B0 = xB[lane], B1 = xB[32 + lane];
    float4 C0 = xC[lane], C1 = xC[32 + lane];
    float4 D0 = xD[lane], D1 = xD[32 + lane];

    float acc[4][HH];
    #pragma unroll
    for (int h = 0; h < HH; h++) {
        float4 q0 = *(const float4*)&sq[h * CC + lane * 4];
        float4 q1 = *(const float4*)&sq[h * CC + 128 + lane * 4];
        acc[0][h] = A0.x*q0.x + A0.y*q0.y + A0.z*q0.z + A0.w*q0.w
                  + A1.x*q1.x + A1.y*q1.y + A1.z*q1.z + A1.w*q1.w;
        acc[1][h] = B0.x*q0.x + B0.y*q0.y + B0.z*q0.z + B0.w*q0.w
                  + B1.x*q1.x + B1.y*q1.y + B1.z*q1.z + B1.w*q1.w;
        acc[2][h] = C0.x*q0.x + C0.y*q0.y + C0.z*q0.z + C0.w*q0.w
                  + C1.x*q1.x + C1.y*q1.y + C1.z*q1.z + C1.w*q1.w;
        acc[3][h] = D0.x*q0.x + D0.y*q0.y + D0.z*q0.z + D0.w*q0.w
                  + D1.x*q1.x + D1.y*q1.y + D1.z*q1.z + D1.w*q1.w;
    }
    #pragma unroll
    for (int off = 16; off > 0; off >>= 1)
        #pragma unroll
        for (int j = 0; j < 4; j++)
            #pragma unroll
            for (int h = 0; h < HH; h++)
                acc[j][h] += __shfl_xor_sync(0xffffffffu, acc[j][h], off);

    if (lane == 0) {
        float qc0 = sqc[0], qc1 = sqc[1], qc2 = sqc[2], qc3 = sqc[3];
        #pragma unroll
        for (int j = 0; j < 4; j++) {
            int n = n0 + j;
            if (n >= N) break;
            int p = poi[n];
            float s0 = acc[j][0] + qc0, s1 = acc[j][1] + qc1;
            float s2 = acc[j][2] + qc2, s3 = acc[j][3] + qc3;
            atomicMax(&g_smax[p * 4 + 0], encf(s0));
            atomicMax(&g_smax[p * 4 + 1], encf(s1));
            atomicMax(&g_smax[p * 4 + 2], encf(s2));
            atomicMax(&g_smax[p * 4 + 3], encf(s3));
            *(float4*)&g_scoreE[(size_t)n * 4] = make_float4(s0, s1, s2, s3);
            int old = atomicExch(&g_head[p], n);   // push onto POI list
            g_next[n] = old;
        }
    }
}

// gather via linked list; denom warp-local; xbar pre-normalized; g_m = d/(d+eps).
__global__ void k_gather(const float* __restrict__ x, int P) {
    int lane = threadIdx.x & 31;
    int p = (blockIdx.x * blockDim.x + threadIdx.x) >> 5;
    if (p >= P) return;

    float a0[HH][4], a1[HH][4];
    #pragma unroll
    for (int h = 0; h < HH; h++)
        #pragma unroll
        for (int k = 0; k < 4; k++) { a0[h][k] = 0.f; a1[h][k] = 0.f; }

    float d0 = 0.f, d1 = 0.f, d2 = 0.f, d3 = 0.f;
    int n = g_head[p];

    if (n >= 0) {
        int hh = lane & 3;
        float m0 = decf(g_smax[p * 4 + 0]);
        float m1 = decf(g_smax[p * 4 + 1]);
        float m2 = decf(g_smax[p * 4 + 2]);
        float m3 = decf(g_smax[p * 4 + 3]);
        float mv = (hh == 0) ? m0 : (hh == 1) ? m1 : (hh == 2) ? m2 : m3;

        while (n >= 0) {
            int nn = __ldg(&g_next[n]);                  // issue chain hop first
            float4 s = *(const float4*)&g_scoreE[(size_t)n * 4];
            const float4* xr = (const float4*)(x + (size_t)n * CC);
            float4 v0 = xr[lane];
            float4 v1 = xr[32 + lane];
            float sv = (hh == 0) ? s.x : (hh == 1) ? s.y : (hh == 2) ? s.z : s.w;
            float ee = expf(sv - mv);
            float e0 = __shfl_sync(0xffffffffu, ee, 0);
            float e1 = __shfl_sync(0xffffffffu, ee, 1);
            float e2 = __shfl_sync(0xffffffffu, ee, 2);
            float e3 = __shfl_sync(0xffffffffu, ee, 3);
            d0 += e0; d1 += e1; d2 += e2; d3 += e3;
            float al[HH] = { e0, e1, e2, e3 };
            #pragma unroll
            for (int h = 0; h < HH; h++) {
                a0[h][0] += al[h] * v0.x; a0[h][1] += al[h] * v0.y;
                a0[h][2] += al[h] * v0.z; a0[h][3] += al[h] * v0.w;
                a1[h][0] += al[h] * v1.x; a1[h][1] += al[h] * v1.y;
                a1[h][2] += al[h] * v1.z; a1[h][3] += al[h] * v1.w;
            }
            n = nn;
        }
    }
    float r[HH] = { 1.f / (d0 + 1e-16f), 1.f / (d1 + 1e-16f),
                    1.f / (d2 + 1e-16f), 1.f / (d3 + 1e-16f) };
    #pragma unroll
    for (int h = 0; h < HH; h++) {
        float* dst = &g_xbar[((size_t)p * HH + h) * CC];
        *(float4*)&dst[lane * 4] = make_float4(a0[h][0]*r[h], a0[h][1]*r[h],
                                               a0[h][2]*r[h], a0[h][3]*r[h]);
        *(float4*)&dst[128 + lane * 4] = make_float4(a1[h][0]*r[h], a1[h][1]*r[h],
                                                     a1[h][2]*r[h], a1[h][3]*r[h]);
    }
    if (lane == 0)
        *(float4*)&g_m[p * 4] = make_float4(d0 / (d0 + 1e-16f), d1 / (d1 + 1e-16f),
                                            d2 / (d2 + 1e-16f), d3 / (d3 + 1e-16f));
}

// Fused GEMMs. TP=16 rows/block, 256 thr, 2 blocks/SM (16 warps).
// Thread = 8 rows x 2 cols (16 ull acc). Weight LDGs software-pipelined.
__global__ void __launch_bounds__(256, 2) k_fused(
    const float* __restrict__ Wv, const float* __restrict__ Wo,
    const float* __restrict__ bv, const float* __restrict__ bo,
    const float* __restrict__ prelu, float* __restrict__ out, int P)
{
    __shared__ float sO[TP * CC];            // 16 KB
    __shared__ float sX[TP * HH * 32];       // 8 KB (k-chunk of xbar)
    int t = threadIdx.x;
    int w = t >> 5, lane = t & 31;
    int head = w & 3;
    int rbase = (w >> 2) * 8;                // 0 or 8
    int c0 = head * 64 + lane * 2;
    int p0 = blockIdx.x * TP;

    ull acc[8][2];
    #pragma unroll
    for (int pp = 0; pp < 8; pp++) { acc[pp][0] = 0ull; acc[pp][1] = 0ull; }

    const float* wv0 = Wv + (size_t)c0 * CC;
    const float* wv1 = Wv + (size_t)(c0 + 1) * CC;

    // ---- Phase A: O = Q + xbar @ Wv^T + bv*m ----
    for (int ch = 0; ch < 8; ch++) {
        int k0 = ch * 32;
        // stage 16 rows x 4 heads x 32 k  (512 float4; 2 per thread; coalesced)
        #pragma unroll
        for (int i = 0; i < 2; i++) {
            int idx = t + i * 256;             // slice*8 + off
            int slice = idx >> 3, off = idx & 7;
            ((float4*)sX)[idx] =
                *(const float4*)&g_xbar[((size_t)p0 * HH + slice) * CC + k0 + off * 4];
        }
        __syncthreads();
        // pipeline weights: load sub=0, prefetch sub+1 before each pp loop
        ull w0[4], w1[4], n0r[4], n1r[4];
        {
            longlong2 a = *(const longlong2*)(wv0 + k0);
            longlong2 b = *(const longlong2*)(wv0 + k0 + 4);
            w0[0] = (ull)a.x; w0[1] = (ull)a.y; w0[2] = (ull)b.x; w0[3] = (ull)b.y;
            longlong2 c = *(const longlong2*)(wv1 + k0);
            longlong2 d = *(const longlong2*)(wv1 + k0 + 4);
            w1[0] = (ull)c.x; w1[1] = (ull)c.y; w1[2] = (ull)d.x; w1[3] = (ull)d.y;
        }
        #pragma unroll
        for (int sub = 0; sub < 4; sub++) {
            if (sub < 3) {
                int kn = k0 + (sub + 1) * 8;
                longlong2 a = *(const longlong2*)(wv0 + kn);
                longlong2 b = *(const longlong2*)(wv0 + kn + 4);
                n0r[0] = (ull)a.x; n0r[1] = (ull)a.y; n0r[2] = (ull)b.x; n0r[3] = (ull)b.y;
                longlong2 c = *(const longlong2*)(wv1 + kn);
                longlong2 d = *(const longlong2*)(wv1 + kn + 4);
                n1r[0] = (ull)c.x; n1r[1] = (ull)c.y; n1r[2] = (ull)d.x; n1r[3] = (ull)d.y;
            }
            #pragma unroll
            for (int pp = 0; pp < 8; pp++) {
                const longlong2* sp =
                    (const longlong2*)&sX[((rbase + pp) * HH + head) * 32 + sub * 8];
                longlong2 a = sp[0], b = sp[1];
                fma2(acc[pp][0], (ull)a.x, w0[0]); fma2(acc[pp][1], (ull)a.x, w1[0]);
                fma2(acc[pp][0], (ull)a.y, w0[1]); fma2(acc[pp][1], (ull)a.y, w1[1]);
                fma2(acc[pp][0], (ull)b.x, w0[2]); fma2(acc[pp][1], (ull)b.x, w1[2]);
                fma2(acc[pp][0], (ull)b.y, w0[3]); fma2(acc[pp][1], (ull)b.y, w1[3]);
            }
            #pragma unroll
            for (int u = 0; u < 4; u++) { w0[u] = n0r[u]; w1[u] = n1r[u]; }
        }
        __syncthreads();
    }
    {
        float q0v = g_Q[c0], q1v = g_Q[c0 + 1];
        float b0v = bv[c0], b1v = bv[c0 + 1];
        #pragma unroll
        for (int pp = 0; pp < 8; pp++) {
            float m = g_m[(p0 + rbase + pp) * 4 + head];     // padded: safe
            float2 o = make_float2(hadd2(acc[pp][0]) + q0v + b0v * m,
                                   hadd2(acc[pp][1]) + q1v + b1v * m);
            *(float2*)&sO[(rbase + pp) * CC + c0] = o;
            acc[pp][0] = 0ull; acc[pp][1] = 0ull;
        }
    }
    __syncthreads();

    // ---- Phase B: out = prelu(O + relu(O @ Wo^T + bo)) ----
    const float* wo0 = Wo + (size_t)c0 * CC;
    const float* wo1 = Wo + (size_t)(c0 + 1) * CC;
    {
        ull w0[4], w1[4], n0r[4], n1r[4];
        {
            longlong2 a = *(const longlong2*)(wo0);
            longlong2 b = *(const longlong2*)(wo0 + 4);
            w0[0] = (ull)a.x; w0[1] = (ull)a.y; w0[2] = (ull)b.x; w0[3] = (ull)b.y;
            longlong2 c = *(const longlong2*)(wo1);
            longlong2 d = *(const longlong2*)(wo1 + 4);
            w1[0] = (ull)c.x; w1[1] = (ull)c.y; w1[2] = (ull)d.x; w1[3] = (ull)d.y;
        }
        for (int kc = 0; kc < CC / 8; kc++) {
            if (kc < CC / 8 - 1) {
                int kn = (kc + 1) * 8;
                longlong2 a = *(const longlong2*)(wo0 + kn);
                longlong2 b = *(const longlong2*)(wo0 + kn + 4);
                n0r[0] = (ull)a.x; n0r[1] = (ull)a.y; n0r[2] = (ull)b.x; n0r[3] = (ull)b.y;
                longlong2 c = *(const longlong2*)(wo1 + kn);
                longlong2 d = *(const longlong2*)(wo1 + kn + 4);
                n1r[0] = (ull)c.x; n1r[1] = (ull)c.y; n1r[2] = (ull)d.x; n1r[3] = (ull)d.y;
            }
            int kk = kc * 8;
            #pragma unroll
            for (int pp = 0; pp < 8; pp++) {
                const longlong2* sp = (const longlong2*)&sO[(rbase + pp) * CC + kk];
                longlong2 a = sp[0], b = sp[1];
                fma2(acc[pp][0], (ull)a.x, w0[0]); fma2(acc[pp][1], (ull)a.x, w1[0]);
                fma2(acc[pp][0], (ull)a.y, w0[1]); fma2(acc[pp][1], (ull)a.y, w1[1]);
                fma2(acc[pp][0], (ull)b.x, w0[2]); fma2(acc[pp][1], (ull)b.x, w1[2]);
                fma2(acc[pp][0], (ull)b.y, w0[3]); fma2(acc[pp][1], (ull)b.y, w1[3]);
            }
            #pragma unroll
            for (int u = 0; u < 4; u++) { w0[u] = n0r[u]; w1[u] = n1r[u]; }
        }
    }
    {
        float bo0 = bo[c0], bo1 = bo[c0 + 1];
        float pa = prelu[0];
        #pragma unroll
        for (int pp = 0; pp < 8; pp++) {
            int p = p0 + rbase + pp;
            if (p < P) {
                float2 o = *(const float2*)&sO[(rbase + pp) * CC + c0];
                float t0 = fmaxf(hadd2(acc[pp][0]) + bo0, 0.f);
                float t1 = fmaxf(hadd2(acc[pp][1]) + bo1, 0.f);
                float r0 = o.x + t0; r0 = (r0 >= 0.f) ? r0 : pa * r0;
                float r1 = o.y + t1; r1 = (r1 >= 0.f) ? r1 : pa * r1;
                *(float2*)&out[(size_t)p * CC + c0] = make_float2(r0, r1);
            }
        }
    }
}

// ---------------- launch ----------------
extern "C" void kernel_launch(void* const* d_in, const int* in_sizes, int n_in,
                              void* d_out, int out_size) {
    int off = (n_in >= 13) ? 1 : 0;
    const float* x   = (const float*)d_in[0];
    const int*   poi = (const int*)d_in[1];
    const float* Wq  = (const float*)d_in[2 + off];
    const float* bq  = (const float*)d_in[3 + off];
    const float* Wk  = (const float*)d_in[4 + off];
    const float* bk  = (const float*)d_in[5 + off];
    const float* Wv  = (const float*)d_in[6 + off];
    const float* bv  = (const float*)d_in[7 + off];
    const float* Wo  = (const float*)d_in[8 + off];
    const float* bo  = (const float*)d_in[9 + off];
    const float* S   = (const float*)d_in[10 + off];
    const float* pa  = (const float*)d_in[11 + off];
    float* out = (float*)d_out;

    int N = in_sizes[0] / CC;
    int P = out_size / CC;

    k_init_prep<<<257, 256>>>(S, Wq, bq, Wk, bk, P);   // 1
    k_scores<<<(N + 31) / 32, 256>>>(x, poi, N);       // 2 (incl. list scatter)
    k_gather<<<(P + 7) / 8, 256>>>(x, P);              // 3
    k_fused<<<(P + TP - 1) / TP, 256>>>(Wv, Wo, bv, bo, pa, out, P);  // 4 -> profiled
}

// round 10
// speedup vs baseline: 1.8032x; 1.8032x over previous
#include <cuda_runtime.h>
#include <math.h>

#define CC 256
#define HH 4
#define NMAX 500000
#define PMAX 50000
#define TP 16

typedef unsigned long long ull;

// ---------------- device scratch ----------------
__device__ float     g_Q[CC];
__device__ float     g_qw[HH * CC];
__device__ float     g_qc[HH];
__device__ float     g_scoreE[(size_t)NMAX * HH];          // raw scores
__device__ unsigned  g_smax[PMAX * HH];
__device__ float     g_m[(PMAX + 32) * HH];                // m = d/(d+eps); padded
__device__ int       g_head[PMAX];                         // linked-list heads
__device__ int       g_next[NMAX];
__device__ float     g_xbar[(size_t)(PMAX + 32) * HH * CC]; // pre-normalized; padded
// packed transposed weights: [kp (128)][c/2 (128)] ; .x = cols c pair(k,k+1), .y = col c+1
__device__ longlong2 g_WvP[128 * 128];
__device__ longlong2 g_WoP[128 * 128];

// ---------------- helpers ----------------
__device__ __forceinline__ unsigned encf(float f) {
    unsigned u = __float_as_uint(f);
    return (u & 0x80000000u) ? ~u : (u | 0x80000000u);
}
__device__ __forceinline__ float decf(unsigned u) {
    return (u & 0x80000000u) ? __uint_as_float(u ^ 0x80000000u) : __uint_as_float(~u);
}
__device__ __forceinline__ float hadd2(ull v) {
    float x, y;
    asm("mov.b64 {%0,%1}, %2;" : "=f"(x), "=f"(y) : "l"(v));
    return x + y;
}
__device__ __forceinline__ ull pk2(float x, float y) {
    ull r;
    asm("mov.b64 %0, {%1,%2};" : "=l"(r) : "f"(x), "f"(y));
    return r;
}
__device__ __forceinline__ void fma2(ull& d, ull a, ull b) {
    asm("fma.rn.f32x2 %0, %1, %2, %0;" : "+l"(d) : "l"(a), "l"(b));
}

// ---------------- kernels ----------------

// block 0: Q = S@Wq^T+bq, qw/qc.  blocks 1..: clear smax/head.
__global__ void k_init_prep(const float* __restrict__ S, const float* __restrict__ Wq,
                            const float* __restrict__ bq, const float* __restrict__ Wk,
                            const float* __restrict__ bk, int P)
{
    int t = threadIdx.x;
    if (blockIdx.x == 0) {
        __shared__ float sS[CC];
        __shared__ float sQ[CC];
        sS[t] = S[t];
        __syncthreads();
        const float4* wr = (const float4*)(Wq + (size_t)t * CC);
        float acc = 0.f;
        #pragma unroll 8
        for (int j = 0; j < CC / 4; j++) {
            float4 w = wr[j];
            acc += sS[4*j] * w.x + sS[4*j+1] * w.y + sS[4*j+2] * w.z + sS[4*j+3] * w.w;
        }
        acc += bq[t];
        sQ[t] = acc;
        g_Q[t] = acc;
        __syncthreads();
        #pragma unroll
        for (int h = 0; h < HH; h++) {
            float a = 0.f;
            #pragma unroll 8
            for (int cc = 0; cc < 64; cc++)
                a += sQ[h * 64 + cc] * Wk[(size_t)(h * 64 + cc) * CC + t];
            g_qw[h * CC + t] = a * 0.0625f;
        }
        if (t < HH) {
            float q = 0.f;
            for (int cc = 0; cc < 64; cc++) q += sQ[t * 64 + cc] * bk[t * 64 + cc];
            g_qc[t] = q * 0.0625f;
        }
    } else {
        int i = (blockIdx.x - 1) * blockDim.x + t;
        int st = (gridDim.x - 1) * blockDim.x;
        for (int j = i; j < P * HH; j += st) g_smax[j] = 0u;
        for (int j = i; j < P; j += st) g_head[j] = -1;
    }
}

// pack Wv/Wo into transposed k-paired layout (one-shot, ~1MB)
__global__ void k_pack(const float* __restrict__ Wv, const float* __restrict__ Wo) {
    int idx = blockIdx.x * blockDim.x + threadIdx.x;   // 0..16383
    int kp = idx >> 7, ch = idx & 127;
    int c = ch * 2, k = kp * 2;
    float2 a0 = *(const float2*)&Wv[(size_t)c * CC + k];
    float2 a1 = *(const float2*)&Wv[(size_t)(c + 1) * CC + k];
    longlong2 r;
    r.x = (long long)pk2(a0.x, a0.y);
    r.y = (long long)pk2(a1.x, a1.y);
    g_WvP[idx] = r;
    float2 b0 = *(const float2*)&Wo[(size_t)c * CC + k];
    float2 b1 = *(const float2*)&Wo[(size_t)(c + 1) * CC + k];
    longlong2 s;
    s.x = (long long)pk2(b0.x, b0.y);
    s.y = (long long)pk2(b1.x, b1.y);
    g_WoP[idx] = s;
}

// warp handles 4 checkins (MLP=8); also pushes n onto POI linked list.
__global__ void __launch_bounds__(256) k_scores(
    const float* __restrict__ x, const int* __restrict__ poi, int N)
{
    __shared__ float sq[HH * CC];
    __shared__ float sqc[HH];
    int t = threadIdx.x;
    *(float4*)&sq[t * 4] = *(const float4*)&g_qw[t * 4];
    if (t < HH) sqc[t] = g_qc[t];
    __syncthreads();

    int lane = t & 31;
    int gw = (blockIdx.x * blockDim.x + t) >> 5;
    int n0 = gw * 4;
    if (n0 >= N) return;
    int nA = n0, nB = min(n0 + 1, N - 1), nC = min(n0 + 2, N - 1), nD = min(n0 + 3, N - 1);

    const float4* xA = (const float4*)(x + (size_t)nA * CC);
    const float4* xB = (const float4*)(x + (size_t)nB * CC);
    const float4* xC = (const float4*)(x + (size_t)nC * CC);
    const float4* xD = (const float4*)(x + (size_t)nD * CC);
    float4 A0 = xA[lane], A1 = xA[32 + lane];
    float4 B0 = xB[lane], B1 = xB[32 + lane];
    float4 C0 = xC[lane], C1 = xC[32 + lane];
    float4 D0 = xD[lane], D1 = xD[32 + lane];

    float acc[4][HH];
    #pragma unroll
    for (int h = 0; h < HH; h++) {
        float4 q0 = *(const float4*)&sq[h * CC + lane * 4];
        float4 q1 = *(const float4*)&sq[h * CC + 128 + lane * 4];
        acc[0][h] = A0.x*q0.x + A0.y*q0.y + A0.z*q0.z + A0.w*q0.w
                  + A1.x*q1.x + A1.y*q1.y + A1.z*q1.z + A1.w*q1.w;
        acc[1][h] = B0.x*q0.x + B0.y*q0.y + B0.z*q0.z + B0.w*q0.w
                  + B1.x*q1.x + B1.y*q1.y + B1.z*q1.z + B1.w*q1.w;
        acc[2][h] = C0.x*q0.x + C0.y*q0.y + C0.z*q0.z + C0.w*q0.w
                  + C1.x*q1.x + C1.y*q1.y + C1.z*q1.z + C1.w*q1.w;
        acc[3][h] = D0.x*q0.x + D0.y*q0.y + D0.z*q0.z + D0.w*q0.w
                  + D1.x*q1.x + D1.y*q1.y + D1.z*q1.z + D1.w*q1.w;
    }
    #pragma unroll
    for (int off = 16; off > 0; off >>= 1)
        #pragma unroll
        for (int j = 0; j < 4; j++)
            #pragma unroll
            for (int h = 0; h < HH; h++)
                acc[j][h] += __shfl_xor_sync(0xffffffffu, acc[j][h], off);

    if (lane == 0) {
        float qc0 = sqc[0], qc1 = sqc[1], qc2 = sqc[2], qc3 = sqc[3];
        #pragma unroll
        for (int j = 0; j < 4; j++) {
            int n = n0 + j;
            if (n >= N) break;
            int p = poi[n];
            float s0 = acc[j][0] + qc0, s1 = acc[j][1] + qc1;
            float s2 = acc[j][2] + qc2, s3 = acc[j][3] + qc3;
            atomicMax(&g_smax[p * 4 + 0], encf(s0));
            atomicMax(&g_smax[p * 4 + 1], encf(s1));
            atomicMax(&g_smax[p * 4 + 2], encf(s2));
            atomicMax(&g_smax[p * 4 + 3], encf(s3));
            *(float4*)&g_scoreE[(size_t)n * 4] = make_float4(s0, s1, s2, s3);
            int old = atomicExch(&g_head[p], n);   // push onto POI list
            g_next[n] = old;
        }
    }
}

// gather via linked list; denom warp-local; xbar pre-normalized; g_m = d/(d+eps).
__global__ void k_gather(const float* __restrict__ x, int P) {
    int lane = threadIdx.x & 31;
    int p = (blockIdx.x * blockDim.x + threadIdx.x) >> 5;
    if (p >= P) return;

    float a0[HH][4], a1[HH][4];
    #pragma unroll
    for (int h = 0; h < HH; h++)
        #pragma unroll
        for (int k = 0; k < 4; k++) { a0[h][k] = 0.f; a1[h][k] = 0.f; }

    float d0 = 0.f, d1 = 0.f, d2 = 0.f, d3 = 0.f;
    int n = g_head[p];

    if (n >= 0) {
        int hh = lane & 3;
        float m0 = decf(g_smax[p * 4 + 0]);
        float m1 = decf(g_smax[p * 4 + 1]);
        float m2 = decf(g_smax[p * 4 + 2]);
        float m3 = decf(g_smax[p * 4 + 3]);
        float mv = (hh == 0) ? m0 : (hh == 1) ? m1 : (hh == 2) ? m2 : m3;

        while (n >= 0) {
            int nn = __ldg(&g_next[n]);                  // issue chain hop first
            float4 s = *(const float4*)&g_scoreE[(size_t)n * 4];
            const float4* xr = (const float4*)(x + (size_t)n * CC);
            float4 v0 = xr[lane];
            float4 v1 = xr[32 + lane];
            float sv = (hh == 0) ? s.x : (hh == 1) ? s.y : (hh == 2) ? s.z : s.w;
            float ee = expf(sv - mv);
            float e0 = __shfl_sync(0xffffffffu, ee, 0);
            float e1 = __shfl_sync(0xffffffffu, ee, 1);
            float e2 = __shfl_sync(0xffffffffu, ee, 2);
            float e3 = __shfl_sync(0xffffffffu, ee, 3);
            d0 += e0; d1 += e1; d2 += e2; d3 += e3;
            float al[HH] = { e0, e1, e2, e3 };
            #pragma unroll
            for (int h = 0; h < HH; h++) {
                a0[h][0] += al[h] * v0.x; a0[h][1] += al[h] * v0.y;
                a0[h][2] += al[h] * v0.z; a0[h][3] += al[h] * v0.w;
                a1[h][0] += al[h] * v1.x; a1[h][1] += al[h] * v1.y;
                a1[h][2] += al[h] * v1.z; a1[h][3] += al[h] * v1.w;
            }
            n = nn;
        }
    }
    float r[HH] = { 1.f / (d0 + 1e-16f), 1.f / (d1 + 1e-16f),
                    1.f / (d2 + 1e-16f), 1.f / (d3 + 1e-16f) };
    #pragma unroll
    for (int h = 0; h < HH; h++) {
        float* dst = &g_xbar[((size_t)p * HH + h) * CC];
        *(float4*)&dst[lane * 4] = make_float4(a0[h][0]*r[h], a0[h][1]*r[h],
                                               a0[h][2]*r[h], a0[h][3]*r[h]);
        *(float4*)&dst[128 + lane * 4] = make_float4(a1[h][0]*r[h], a1[h][1]*r[h],
                                                     a1[h][2]*r[h], a1[h][3]*r[h]);
    }
    if (lane == 0)
        *(float4*)&g_m[p * 4] = make_float4(d0 / (d0 + 1e-16f), d1 / (d1 + 1e-16f),
                                            d2 / (d2 + 1e-16f), d3 / (d3 + 1e-16f));
}

// Fused GEMMs. TP=16 rows, 256 thr, 2 blocks/SM.
// Weights from packed-transposed g_WvP/g_WoP: one coalesced LDG.128 yields
// the exact (col0-pair, col1-pair) fma2 operands.
__global__ void __launch_bounds__(256, 2) k_fused(
    const float* __restrict__ bv, const float* __restrict__ bo,
    const float* __restrict__ prelu, float* __restrict__ out, int P)
{
    __shared__ float sO[TP * CC];            // 16 KB
    __shared__ float sX[TP * HH * 32];       // 8 KB (k-chunk of xbar)
    int t = threadIdx.x;
    int w = t >> 5, lane = t & 31;
    int head = w & 3;
    int rbase = (w >> 2) * 8;                // 0 or 8
    int c0 = head * 64 + lane * 2;
    int p0 = blockIdx.x * TP;

    ull acc[8][2];
    #pragma unroll
    for (int pp = 0; pp < 8; pp++) { acc[pp][0] = 0ull; acc[pp][1] = 0ull; }

    const longlong2* wvp = g_WvP + (c0 >> 1);   // element stride 128 per kp

    // ---- Phase A: O = Q + xbar @ Wv^T + bv*m ----
    for (int ch = 0; ch < 8; ch++) {
        int k0 = ch * 32;
        // stage 16 rows x 4 heads x 32 k  (512 float4; 2 per thread; coalesced)
        #pragma unroll
        for (int i = 0; i < 2; i++) {
            int idx = t + i * 256;             // slice*8 + off
            int slice = idx >> 3, off = idx & 7;
            ((float4*)sX)[idx] =
                *(const float4*)&g_xbar[((size_t)p0 * HH + slice) * CC + k0 + off * 4];
        }
        __syncthreads();
        int kp0 = ch * 16;
        ull w0[4], w1[4], n0r[4], n1r[4];
        #pragma unroll
        for (int u = 0; u < 4; u++) {
            longlong2 v = wvp[(kp0 + u) * 128];
            w0[u] = (ull)v.x; w1[u] = (ull)v.y;
        }
        #pragma unroll
        for (int sub = 0; sub < 4; sub++) {
            if (sub < 3) {
                int kpn = kp0 + (sub + 1) * 4;
                #pragma unroll
                for (int u = 0; u < 4; u++) {
                    longlong2 v = wvp[(kpn + u) * 128];
                    n0r[u] = (ull)v.x; n1r[u] = (ull)v.y;
                }
            }
            #pragma unroll
            for (int pp = 0; pp < 8; pp++) {
                const longlong2* sp =
                    (const longlong2*)&sX[((rbase + pp) * HH + head) * 32 + sub * 8];
                longlong2 a = sp[0], b = sp[1];
                fma2(acc[pp][0], (ull)a.x, w0[0]); fma2(acc[pp][1], (ull)a.x, w1[0]);
                fma2(acc[pp][0], (ull)a.y, w0[1]); fma2(acc[pp][1], (ull)a.y, w1[1]);
                fma2(acc[pp][0], (ull)b.x, w0[2]); fma2(acc[pp][1], (ull)b.x, w1[2]);
                fma2(acc[pp][0], (ull)b.y, w0[3]); fma2(acc[pp][1], (ull)b.y, w1[3]);
            }
            #pragma unroll
            for (int u = 0; u < 4; u++) { w0[u] = n0r[u]; w1[u] = n1r[u]; }
        }
        __syncthreads();
    }
    {
        float q0v = g_Q[c0], q1v = g_Q[c0 + 1];
        float b0v = bv[c0], b1v = bv[c0 + 1];
        #pragma unroll
        for (int pp = 0; pp < 8; pp++) {
            float m = g_m[(p0 + rbase + pp) * 4 + head];     // padded: safe
            float2 o = make_float2(hadd2(acc[pp][0]) + q0v + b0v * m,
                                   hadd2(acc[pp][1]) + q1v + b1v * m);
            *(float2*)&sO[(rbase + pp) * CC + c0] = o;
            acc[pp][0] = 0ull; acc[pp][1] = 0ull;
        }
    }
    __syncthreads();

    // ---- Phase B: out = prelu(O + relu(O @ Wo^T + bo)) ----
    const longlong2* wop = g_WoP + (c0 >> 1);
    {
        ull w0[4], w1[4], n0r[4], n1r[4];
        #pragma unroll
        for (int u = 0; u < 4; u++) {
            longlong2 v = wop[u * 128];
            w0[u] = (ull)v.x; w1[u] = (ull)v.y;
        }
        for (int kc = 0; kc < CC / 8; kc++) {
            if (kc < CC / 8 - 1) {
                int kpn = (kc + 1) * 4;
                #pragma unroll
                for (int u = 0; u < 4; u++) {
                    longlong2 v = wop[(kpn + u) * 128];
                    n0r[u] = (ull)v.x; n1r[u] = (ull)v.y;
                }
            }
            int kk = kc * 8;
            #pragma unroll
            for (int pp = 0; pp < 8; pp++) {
                const longlong2* sp = (const longlong2*)&sO[(rbase + pp) * CC + kk];
                longlong2 a = sp[0], b = sp[1];
                fma2(acc[pp][0], (ull)a.x, w0[0]); fma2(acc[pp][1], (ull)a.x, w1[0]);
                fma2(acc[pp][0], (ull)a.y, w0[1]); fma2(acc[pp][1], (ull)a.y, w1[1]);
                fma2(acc[pp][0], (ull)b.x, w0[2]); fma2(acc[pp][1], (ull)b.x, w1[2]);
                fma2(acc[pp][0], (ull)b.y, w0[3]); fma2(acc[pp][1], (ull)b.y, w1[3]);
            }
            #pragma unroll
            for (int u = 0; u < 4; u++) { w0[u] = n0r[u]; w1[u] = n1r[u]; }
        }
    }
    {
        float bo0 = bo[c0], bo1 = bo[c0 + 1];
        float pa = prelu[0];
        #pragma unroll
        for (int pp = 0; pp < 8; pp++) {
            int p = p0 + rbase + pp;
            if (p < P) {
                float2 o = *(const float2*)&sO[(rbase + pp) * CC + c0];
                float t0 = fmaxf(hadd2(acc[pp][0]) + bo0, 0.f);
                float t1 = fmaxf(hadd2(acc[pp][1]) + bo1, 0.f);
                float r0 = o.x + t0; r0 = (r0 >= 0.f) ? r0 : pa * r0;
                float r1 = o.y + t1; r1 = (r1 >= 0.f) ? r1 : pa * r1;
                *(float2*)&out[(size_t)p * CC + c0] = make_float2(r0, r1);
            }
        }
    }
}

// ---------------- launch ----------------
extern "C" void kernel_launch(void* const* d_in, const int* in_sizes, int n_in,
                              void* d_out, int out_size) {
    int off = (n_in >= 13) ? 1 : 0;
    const float* x   = (const float*)d_in[0];
    const int*   poi = (const int*)d_in[1];
    const float* Wq  = (const float*)d_in[2 + off];
    const float* bq  = (const float*)d_in[3 + off];
    const float* Wk  = (const float*)d_in[4 + off];
    const float* bk  = (const float*)d_in[5 + off];
    const float* Wv  = (const float*)d_in[6 + off];
    const float* bv  = (const float*)d_in[7 + off];
    const float* Wo  = (const float*)d_in[8 + off];
    const float* bo  = (const float*)d_in[9 + off];
    const float* S   = (const float*)d_in[10 + off];
    const float* pa  = (const float*)d_in[11 + off];
    float* out = (float*)d_out;

    int N = in_sizes[0] / CC;
    int P = out_size / CC;

    k_init_prep<<<257, 256>>>(S, Wq, bq, Wk, bk, P);   // 1
    k_pack<<<64, 256>>>(Wv, Wo);                       // 2
    k_scores<<<(N + 31) / 32, 256>>>(x, poi, N);       // 3
    k_gather<<<(P + 7) / 8, 256>>>(x, P);              // 4 -> profiled
    k_fused<<<(P + TP - 1) / TP, 256>>>(bv, bo, pa, out, P);  // 5
}

// round 11
// speedup vs baseline: 1.8088x; 1.0031x over previous
#include <cuda_runtime.h>
#include <math.h>

#define CC 256
#define HH 4
#define NMAX 500000
#define PMAX 50000
#define TP 16

typedef unsigned long long ull;

// ---------------- device scratch ----------------
__device__ float     g_Q[CC];
__device__ float     g_qw[HH * CC];
__device__ float     g_qc[HH];
__device__ float     g_scoreE[(size_t)NMAX * HH];          // raw scores
__device__ unsigned  g_smax[PMAX * HH];
__device__ float     g_m[(PMAX + 32) * HH];                // m = d/(d+eps); padded
__device__ int       g_head[PMAX];                         // linked-list heads
__device__ int       g_next[NMAX];
__device__ float     g_xbar[(size_t)(PMAX + 32) * HH * CC]; // pre-normalized; padded
// packed transposed weights: [kp (128)][c/2 (128)] ; .x = cols c pair(k,k+1), .y = col c+1
__device__ longlong2 g_WvP[128 * 128];
__device__ longlong2 g_WoP[128 * 128];

// ---------------- helpers ----------------
__device__ __forceinline__ unsigned encf(float f) {
    unsigned u = __float_as_uint(f);
    return (u & 0x80000000u) ? ~u : (u | 0x80000000u);
}
__device__ __forceinline__ float decf(unsigned u) {
    return (u & 0x80000000u) ? __uint_as_float(u ^ 0x80000000u) : __uint_as_float(~u);
}
__device__ __forceinline__ float hadd2(ull v) {
    float x, y;
    asm("mov.b64 {%0,%1}, %2;" : "=f"(x), "=f"(y) : "l"(v));
    return x + y;
}
__device__ __forceinline__ ull pk2(float x, float y) {
    ull r;
    asm("mov.b64 %0, {%1,%2};" : "=l"(r) : "f"(x), "f"(y));
    return r;
}
__device__ __forceinline__ void fma2(ull& d, ull a, ull b) {
    asm("fma.rn.f32x2 %0, %1, %2, %0;" : "+l"(d) : "l"(a), "l"(b));
}

// ---------------- kernels ----------------

// block 0: Q = S@Wq^T+bq, qw/qc.  blocks 1..: clear smax/head.
__global__ void k_init_prep(const float* __restrict__ S, const float* __restrict__ Wq,
                            const float* __restrict__ bq, const float* __restrict__ Wk,
                            const float* __restrict__ bk, int P)
{
    int t = threadIdx.x;
    if (blockIdx.x == 0) {
        __shared__ float sS[CC];
        __shared__ float sQ[CC];
        sS[t] = S[t];
        __syncthreads();
        const float4* wr = (const float4*)(Wq + (size_t)t * CC);
        float acc = 0.f;
        #pragma unroll 8
        for (int j = 0; j < CC / 4; j++) {
            float4 w = wr[j];
            acc += sS[4*j] * w.x + sS[4*j+1] * w.y + sS[4*j+2] * w.z + sS[4*j+3] * w.w;
        }
        acc += bq[t];
        sQ[t] = acc;
        g_Q[t] = acc;
        __syncthreads();
        #pragma unroll
        for (int h = 0; h < HH; h++) {
            float a = 0.f;
            #pragma unroll 8
            for (int cc = 0; cc < 64; cc++)
                a += sQ[h * 64 + cc] * Wk[(size_t)(h * 64 + cc) * CC + t];
            g_qw[h * CC + t] = a * 0.0625f;
        }
        if (t < HH) {
            float q = 0.f;
            for (int cc = 0; cc < 64; cc++) q += sQ[t * 64 + cc] * bk[t * 64 + cc];
            g_qc[t] = q * 0.0625f;
        }
    } else {
        int i = (blockIdx.x - 1) * blockDim.x + t;
        int st = (gridDim.x - 1) * blockDim.x;
        for (int j = i; j < P * HH; j += st) g_smax[j] = 0u;
        for (int j = i; j < P; j += st) g_head[j] = -1;
    }
}

// pack Wv/Wo into transposed k-paired layout (one-shot, ~1MB)
__global__ void k_pack(const float* __restrict__ Wv, const float* __restrict__ Wo) {
    int idx = blockIdx.x * blockDim.x + threadIdx.x;   // 0..16383
    int kp = idx >> 7, ch = idx & 127;
    int c = ch * 2, k = kp * 2;
    float2 a0 = *(const float2*)&Wv[(size_t)c * CC + k];
    float2 a1 = *(const float2*)&Wv[(size_t)(c + 1) * CC + k];
    longlong2 r;
    r.x = (long long)pk2(a0.x, a0.y);
    r.y = (long long)pk2(a1.x, a1.y);
    g_WvP[idx] = r;
    float2 b0 = *(const float2*)&Wo[(size_t)c * CC + k];
    float2 b1 = *(const float2*)&Wo[(size_t)(c + 1) * CC + k];
    longlong2 s;
    s.x = (long long)pk2(b0.x, b0.y);
    s.y = (long long)pk2(b1.x, b1.y);
    g_WoP[idx] = s;
}

// warp handles 4 checkins (MLP=8); also pushes n onto POI linked list.
__global__ void __launch_bounds__(256) k_scores(
    const float* __restrict__ x, const int* __restrict__ poi, int N)
{
    __shared__ float sq[HH * CC];
    __shared__ float sqc[HH];
    int t = threadIdx.x;
    *(float4*)&sq[t * 4] = *(const float4*)&g_qw[t * 4];
    if (t < HH) sqc[t] = g_qc[t];
    __syncthreads();

    int lane = t & 31;
    int gw = (blockIdx.x * blockDim.x + t) >> 5;
    int n0 = gw * 4;
    if (n0 >= N) return;
    int nA = n0, nB = min(n0 + 1, N - 1), nC = min(n0 + 2, N - 1), nD = min(n0 + 3, N - 1);

    const float4* xA = (const float4*)(x + (size_t)nA * CC);
    const float4* xB = (const float4*)(x + (size_t)nB * CC);
    const float4* xC = (const float4*)(x + (size_t)nC * CC);
    const float4* xD = (const float4*)(x + (size_t)nD * CC);
    float4 A0 = xA[lane], A1 = xA[32 + lane];
    float4 B0 = xB[lane], B1 = xB[32 + lane];
    float4 C0 = xC[lane], C1 = xC[32 + lane];
    float4 D0 = xD[lane], D1 = xD[32 + lane];

    float acc[4][HH];
    #pragma unroll
    for (int h = 0; h < HH; h++) {
        float4 q0 = *(const float4*)&sq[h * CC + lane * 4];
        float4 q1 = *(const float4*)&sq[h * CC + 128 + lane * 4];
        acc[0][h] = A0.x*q0.x + A0.y*q0.y + A0.z*q0.z + A0.w*q0.w
                  + A1.x*q1.x + A1.y*q1.y + A1.z*q1.z + A1.w*q1.w;
        acc[1][h] = B0.x*q0.x + B0.y*q0.y + B0.z*q0.z + B0.w*q0.w
                  + B1.x*q1.x + B1.y*q1.y + B1.z*q1.z + B1.w*q1.w;
        acc[2][h] = C0.x*q0.x + C0.y*q0.y + C0.z*q0.z + C0.w*q0.w
                  + C1.x*q1.x + C1.y*q1.y + C1.z*q1.z + C1.w*q1.w;
        acc[3][h] = D0.x*q0.x + D0.y*q0.y + D0.z*q0.z + D0.w*q0.w
                  + D1.x*q1.x + D1.y*q1.y + D1.z*q1.z + D1.w*q1.w;
    }
    #pragma unroll
    for (int off = 16; off > 0; off >>= 1)
        #pragma unroll
        for (int j = 0; j < 4; j++)
            #pragma unroll
            for (int h = 0; h < HH; h++)
                acc[j][h] += __shfl_xor_sync(0xffffffffu, acc[j][h], off);

    if (lane == 0) {
        float qc0 = sqc[0], qc1 = sqc[1], qc2 = sqc[2], qc3 = sqc[3];
        #pragma unroll
        for (int j = 0; j < 4; j++) {
            int n = n0 + j;
            if (n >= N) break;
            int p = poi[n];
            float s0 = acc[j][0] + qc0, s1 = acc[j][1] + qc1;
            float s2 = acc[j][2] + qc2, s3 = acc[j][3] + qc3;
            atomicMax(&g_smax[p * 4 + 0], encf(s0));
            atomicMax(&g_smax[p * 4 + 1], encf(s1));
            atomicMax(&g_smax[p * 4 + 2], encf(s2));
            atomicMax(&g_smax[p * 4 + 3], encf(s3));
            *(float4*)&g_scoreE[(size_t)n * 4] = make_float4(s0, s1, s2, s3);
            int old = atomicExch(&g_head[p], n);   // push onto POI list
            g_next[n] = old;
        }
    }
}

// gather via linked list; denom warp-local; xbar pre-normalized; g_m = d/(d+eps).
__global__ void k_gather(const float* __restrict__ x, int P) {
    int lane = threadIdx.x & 31;
    int p = (blockIdx.x * blockDim.x + threadIdx.x) >> 5;
    if (p >= P) return;

    float a0[HH][4], a1[HH][4];
    #pragma unroll
    for (int h = 0; h < HH; h++)
        #pragma unroll
        for (int k = 0; k < 4; k++) { a0[h][k] = 0.f; a1[h][k] = 0.f; }

    float d0 = 0.f, d1 = 0.f, d2 = 0.f, d3 = 0.f;
    int n = g_head[p];

    if (n >= 0) {
        int hh = lane & 3;
        float m0 = decf(g_smax[p * 4 + 0]);
        float m1 = decf(g_smax[p * 4 + 1]);
        float m2 = decf(g_smax[p * 4 + 2]);
        float m3 = decf(g_smax[p * 4 + 3]);
        float mv = (hh == 0) ? m0 : (hh == 1) ? m1 : (hh == 2) ? m2 : m3;

        while (n >= 0) {
            int nn = __ldg(&g_next[n]);                  // issue chain hop first
            float4 s = *(const float4*)&g_scoreE[(size_t)n * 4];
            const float4* xr = (const float4*)(x + (size_t)n * CC);
            float4 v0 = xr[lane];
            float4 v1 = xr[32 + lane];
            float sv = (hh == 0) ? s.x : (hh == 1) ? s.y : (hh == 2) ? s.z : s.w;
            float ee = expf(sv - mv);
            float e0 = __shfl_sync(0xffffffffu, ee, 0);
            float e1 = __shfl_sync(0xffffffffu, ee, 1);
            float e2 = __shfl_sync(0xffffffffu, ee, 2);
            float e3 = __shfl_sync(0xffffffffu, ee, 3);
            d0 += e0; d1 += e1; d2 += e2; d3 += e3;
            float al[HH] = { e0, e1, e2, e3 };
            #pragma unroll
            for (int h = 0; h < HH; h++) {
                a0[h][0] += al[h] * v0.x; a0[h][1] += al[h] * v0.y;
                a0[h][2] += al[h] * v0.z; a0[h][3] += al[h] * v0.w;
                a1[h][0] += al[h] * v1.x; a1[h][1] += al[h] * v1.y;
                a1[h][2] += al[h] * v1.z; a1[h][3] += al[h] * v1.w;
            }
            n = nn;
        }
    }
    float r[HH] = { 1.f / (d0 + 1e-16f), 1.f / (d1 + 1e-16f),
                    1.f / (d2 + 1e-16f), 1.f / (d3 + 1e-16f) };
    #pragma unroll
    for (int h = 0; h < HH; h++) {
        float* dst = &g_xbar[((size_t)p * HH + h) * CC];
        *(float4*)&dst[lane * 4] = make_float4(a0[h][0]*r[h], a0[h][1]*r[h],
                                               a0[h][2]*r[h], a0[h][3]*r[h]);
        *(float4*)&dst[128 + lane * 4] = make_float4(a1[h][0]*r[h], a1[h][1]*r[h],
                                                     a1[h][2]*r[h], a1[h][3]*r[h]);
    }
    if (lane == 0)
        *(float4*)&g_m[p * 4] = make_float4(d0 / (d0 + 1e-16f), d1 / (d1 + 1e-16f),
                                            d2 / (d2 + 1e-16f), d3 / (d3 + 1e-16f));
}

// Fused GEMMs. TP=16 rows, 256 thr, 2 blocks/SM.
// Weights from packed-transposed g_WvP/g_WoP: one coalesced LDG.128 yields
// the exact (col0-pair, col1-pair) fma2 operands.
__global__ void __launch_bounds__(256, 2) k_fused(
    const float* __restrict__ bv, const float* __restrict__ bo,
    const float* __restrict__ prelu, float* __restrict__ out, int P)
{
    __shared__ float sO[TP * CC];            // 16 KB
    __shared__ float sX[TP * HH * 32];       // 8 KB (k-chunk of xbar)
    int t = threadIdx.x;
    int w = t >> 5, lane = t & 31;
    int head = w & 3;
    int rbase = (w >> 2) * 8;                // 0 or 8
    int c0 = head * 64 + lane * 2;
    int p0 = blockIdx.x * TP;

    ull acc[8][2];
    #pragma unroll
    for (int pp = 0; pp < 8; pp++) { acc[pp][0] = 0ull; acc[pp][1] = 0ull; }

    const longlong2* wvp = g_WvP + (c0 >> 1);   // element stride 128 per kp

    // ---- Phase A: O = Q + xbar @ Wv^T + bv*m ----
    for (int ch = 0; ch < 8; ch++) {
        int k0 = ch * 32;
        // stage 16 rows x 4 heads x 32 k  (512 float4; 2 per thread; coalesced)
        #pragma unroll
        for (int i = 0; i < 2; i++) {
            int idx = t + i * 256;             // slice*8 + off
            int slice = idx >> 3, off = idx & 7;
            ((float4*)sX)[idx] =
                *(const float4*)&g_xbar[((size_t)p0 * HH + slice) * CC + k0 + off * 4];
        }
        __syncthreads();
        int kp0 = ch * 16;
        ull w0[4], w1[4], n0r[4], n1r[4];
        #pragma unroll
        for (int u = 0; u < 4; u++) {
            longlong2 v = wvp[(kp0 + u) * 128];
            w0[u] = (ull)v.x; w1[u] = (ull)v.y;
        }
        #pragma unroll
        for (int sub = 0; sub < 4; sub++) {
            if (sub < 3) {
                int kpn = kp0 + (sub + 1) * 4;
                #pragma unroll
                for (int u = 0; u < 4; u++) {
                    longlong2 v = wvp[(kpn + u) * 128];
                    n0r[u] = (ull)v.x; n1r[u] = (ull)v.y;
                }
            }
            #pragma unroll
            for (int pp = 0; pp < 8; pp++) {
                const longlong2* sp =
                    (const longlong2*)&sX[((rbase + pp) * HH + head) * 32 + sub * 8];
                longlong2 a = sp[0], b = sp[1];
                fma2(acc[pp][0], (ull)a.x, w0[0]); fma2(acc[pp][1], (ull)a.x, w1[0]);
                fma2(acc[pp][0], (ull)a.y, w0[1]); fma2(acc[pp][1], (ull)a.y, w1[1]);
                fma2(acc[pp][0], (ull)b.x, w0[2]); fma2(acc[pp][1], (ull)b.x, w1[2]);
                fma2(acc[pp][0], (ull)b.y, w0[3]); fma2(acc[pp][1], (ull)b.y, w1[3]);
            }
            #pragma unroll
            for (int u = 0; u < 4; u++) { w0[u] = n0r[u]; w1[u] = n1r[u]; }
        }
        __syncthreads();
    }
    {
        float q0v = g_Q[c0], q1v = g_Q[c0 + 1];
        float b0v = bv[c0], b1v = bv[c0 + 1];
        #pragma unroll
        for (int pp = 0; pp < 8; pp++) {
            float m = g_m[(p0 + rbase + pp) * 4 + head];     // padded: safe
            float2 o = make_float2(hadd2(acc[pp][0]) + q0v + b0v * m,
                                   hadd2(acc[pp][1]) + q1v + b1v * m);
            *(float2*)&sO[(rbase + pp) * CC + c0] = o;
            acc[pp][0] = 0ull; acc[pp][1] = 0ull;
        }
    }
    __syncthreads();

    // ---- Phase B: out = prelu(O + relu(O @ Wo^T + bo)) ----
    const longlong2* wop = g_WoP + (c0 >> 1);
    {
        ull w0[4], w1[4], n0r[4], n1r[4];
        #pragma unroll
        for (int u = 0; u < 4; u++) {
            longlong2 v = wop[u * 128];
            w0[u] = (ull)v.x; w1[u] = (ull)v.y;
        }
        for (int kc = 0; kc < CC / 8; kc++) {
            if (kc < CC / 8 - 1) {
                int kpn = (kc + 1) * 4;
                #pragma unroll
                for (int u = 0; u < 4; u++) {
                    longlong2 v = wop[(kpn + u) * 128];
                    n0r[u] = (ull)v.x; n1r[u] = (ull)v.y;
                }
            }
            int kk = kc * 8;
            #pragma unroll
            for (int pp = 0; pp < 8; pp++) {
                const longlong2* sp = (const longlong2*)&sO[(rbase + pp) * CC + kk];
                longlong2 a = sp[0], b = sp[1];
                fma2(acc[pp][0], (ull)a.x, w0[0]); fma2(acc[pp][1], (ull)a.x, w1[0]);
                fma2(acc[pp][0], (ull)a.y, w0[1]); fma2(acc[pp][1], (ull)a.y, w1[1]);
                fma2(acc[pp][0], (ull)b.x, w0[2]); fma2(acc[pp][1], (ull)b.x, w1[2]);
                fma2(acc[pp][0], (ull)b.y, w0[3]); fma2(acc[pp][1], (ull)b.y, w1[3]);
            }
            #pragma unroll
            for (int u = 0; u < 4; u++) { w0[u] = n0r[u]; w1[u] = n1r[u]; }
        }
    }
    {
        float bo0 = bo[c0], bo1 = bo[c0 + 1];
        float pa = prelu[0];
        #pragma unroll
        for (int pp = 0; pp < 8; pp++) {
            int p = p0 + rbase + pp;
            if (p < P) {
                float2 o = *(const float2*)&sO[(rbase + pp) * CC + c0];
                float t0 = fmaxf(hadd2(acc[pp][0]) + bo0, 0.f);
                float t1 = fmaxf(hadd2(acc[pp][1]) + bo1, 0.f);
                float r0 = o.x + t0; r0 = (r0 >= 0.f) ? r0 : pa * r0;
                float r1 = o.y + t1; r1 = (r1 >= 0.f) ? r1 : pa * r1;
                *(float2*)&out[(size_t)p * CC + c0] = make_float2(r0, r1);
            }
        }
    }
}

// ---------------- launch ----------------
extern "C" void kernel_launch(void* const* d_in, const int* in_sizes, int n_in,
                              void* d_out, int out_size) {
    int off = (n_in >= 13) ? 1 : 0;
    const float* x   = (const float*)d_in[0];
    const int*   poi = (const int*)d_in[1];
    const float* Wq  = (const float*)d_in[2 + off];
    const float* bq  = (const float*)d_in[3 + off];
    const float* Wk  = (const float*)d_in[4 + off];
    const float* bk  = (const float*)d_in[5 + off];
    const float* Wv  = (const float*)d_in[6 + off];
    const float* bv  = (const float*)d_in[7 + off];
    const float* Wo  = (const float*)d_in[8 + off];
    const float* bo  = (const float*)d_in[9 + off];
    const float* S   = (const float*)d_in[10 + off];
    const float* pa  = (const float*)d_in[11 + off];
    float* out = (float*)d_out;

    int N = in_sizes[0] / CC;
    int P = out_size / CC;

    k_init_prep<<<257, 256>>>(S, Wq, bq, Wk, bk, P);   // 1
    k_pack<<<64, 256>>>(Wv, Wo);                       // 2
    k_scores<<<(N + 31) / 32, 256>>>(x, poi, N);       // 3
    k_gather<<<(P + 7) / 8, 256>>>(x, P);              // 4 -> profiled
    k_fused<<<(P + TP - 1) / TP, 256>>>(bv, bo, pa, out, P);  // 5
}